// round 16
// baseline (speedup 1.0000x reference)
#include <cuda_runtime.h>
#include <cuda_bf16.h>

#define NN 65536      // total nodes
#define EE 1048576    // total edges
#define NB 128        // graphs
#define NPG 512       // nodes per graph
#define EPG 8192      // edges per graph (N*DEG)
#define EPGP 10240    // padded edges per graph (rows padded to x4)
#define FD 128        // feature dim

// ---------------- device scratch ----------------
__device__ __align__(256) float d_X[NN * FD];
__device__ __align__(256) float d_H[NN * FD];
__device__ __align__(256) float d_score[NN];
__device__ __align__(256) float d_sraw[NN];
__device__ __align__(256) float d_dinv[NN];
__device__ __align__(256) float d_dinvm[NN];
__device__ __align__(256) unsigned short d_csr16[NB * EPGP];
__device__ __align__(256) unsigned short d_goff[NB * (NPG + 1)];
__device__ __align__(256) int   d_alive[NB * 256];
__device__ __align__(256) float d_hg[NB * 256];

// ---------------- per-graph CSR build (rows padded to x4) + layer-1 dinv + init ------
__global__ void __launch_bounds__(512) k_csr(const int* __restrict__ src,
                                             const int* __restrict__ dst) {
    __shared__ unsigned short s_src[EPG];
    __shared__ unsigned short s_dst[EPG];
    __shared__ int cnt[NPG];
    __shared__ int scn[NPG];
    __shared__ int cur[NPG];
    int g = blockIdx.x, tid = threadIdx.x;
    int gb = g * NPG, eb = g * EPG, ebp = g * EPGP;

    cnt[tid] = 0;
    for (int e = tid; e < EPG; e += 512) {
        s_src[e] = (unsigned short)(src[eb + e] - gb);
        s_dst[e] = (unsigned short)(dst[eb + e] - gb);
    }
    __syncthreads();
    for (int e = tid; e < EPG; e += 512) atomicAdd(&cnt[s_dst[e]], 1);
    __syncthreads();
    int c = cnt[tid];
    int cp = (c + 3) & ~3;                 // padded row length
    scn[tid] = cp;
    __syncthreads();
    for (int o = 1; o < 512; o <<= 1) {
        int a = scn[tid];
        int b = (tid >= o) ? scn[tid - o] : 0;
        __syncthreads();
        scn[tid] = a + b;
        __syncthreads();
    }
    int excl = scn[tid] - cp;
    cur[tid] = excl;
    d_goff[g * (NPG + 1) + tid] = (unsigned short)excl;
    if (tid == 511) d_goff[g * (NPG + 1) + NPG] = (unsigned short)scn[511];

    for (int j = excl + c; j < excl + cp; j++) d_csr16[ebp + j] = (unsigned short)NPG;

    float dv = rsqrtf((float)(1 + c));
    d_dinv[gb + tid] = dv;
    d_dinvm[gb + tid] = dv;

    d_sraw[gb + tid] = 0.f;
    if (tid < 256) d_hg[g * 256 + tid] = 0.f;
    __syncthreads();
    for (int e = tid; e < EPG; e += 512) {
        int d = s_dst[e];
        int pos = atomicAdd(&cur[d], 1);
        d_csr16[ebp + pos] = s_src[e];
    }
}

// ---------------- tensor-core GEMM: H[rows] = gate*A[rows] @ W -------------------
__device__ __forceinline__ void ldsm_x4(unsigned addr, unsigned& r0, unsigned& r1,
                                        unsigned& r2, unsigned& r3) {
    asm volatile("ldmatrix.sync.aligned.m8n8.x4.shared.b16 {%0,%1,%2,%3}, [%4];"
                 : "=r"(r0), "=r"(r1), "=r"(r2), "=r"(r3) : "r"(addr));
}
__device__ __forceinline__ void ldsm_x4t(unsigned addr, unsigned& r0, unsigned& r1,
                                         unsigned& r2, unsigned& r3) {
    asm volatile("ldmatrix.sync.aligned.m8n8.x4.trans.shared.b16 {%0,%1,%2,%3}, [%4];"
                 : "=r"(r0), "=r"(r1), "=r"(r2), "=r"(r3) : "r"(addr));
}
__device__ __forceinline__ void mma16816(float* c, unsigned a0, unsigned a1,
                                         unsigned a2, unsigned a3,
                                         unsigned b0, unsigned b1) {
    asm volatile(
        "mma.sync.aligned.m16n8k16.row.col.f32.bf16.bf16.f32 "
        "{%0,%1,%2,%3},{%4,%5,%6,%7},{%8,%9},{%0,%1,%2,%3};"
        : "+f"(c[0]), "+f"(c[1]), "+f"(c[2]), "+f"(c[3])
        : "r"(a0), "r"(a1), "r"(a2), "r"(a3), "r"(b0), "r"(b1));
}

#define APAD 40   // A smem row length (32 used)
#define WPAD 136  // W smem row length (128 used)

template <bool USEIDX, bool GATE>
__global__ void __launch_bounds__(256) k_gemm(const float* __restrict__ Ain,
                                              const float* __restrict__ W) {
    __shared__ __align__(16) __nv_bfloat16 As[2][128][APAD];
    __shared__ __align__(16) __nv_bfloat16 Ws[2][32][WPAD];
    __shared__ int alive_s[128];

    const int tid = threadIdx.x;
    const int gbase = blockIdx.x * 128;

    if (USEIDX && tid < 128) alive_s[tid] = d_alive[gbase + tid];

    const int al_r = tid >> 1, al_k = (tid & 1) * 16;
    const int wl_k = tid >> 3, wl_n = (tid & 7) * 16;
    int garow = USEIDX ? d_alive[gbase + al_r] : (gbase + al_r);
    float gate = GATE ? d_score[garow] : 1.f;
    const float* Arow = (USEIDX ? (const float*)d_X : Ain) + (size_t)garow * FD;

    const int lane = tid & 31, wid = tid >> 5;
    const int m0 = (wid >> 1) * 32;
    const int n0 = (wid & 1) * 64;
    const int quad = lane >> 3, r8 = lane & 7;

    float acc[2][8][4] = {};

#pragma unroll 1
    for (int ck = 0; ck < 4; ck++) {
        if (ck) __syncthreads();
        {
            const float* src = Arow + ck * 32 + al_k;
#pragma unroll
            for (int q = 0; q < 4; q++) {
                float4 v = *(const float4*)&src[q * 4];
                if (GATE) { v.x *= gate; v.y *= gate; v.z *= gate; v.w *= gate; }
                float f[4] = {v.x, v.y, v.z, v.w};
#pragma unroll
                for (int i = 0; i < 4; i++) {
                    __nv_bfloat16 h = __float2bfloat16(f[i]);
                    __nv_bfloat16 l = __float2bfloat16(f[i] - __bfloat162float(h));
                    As[0][al_r][al_k + q * 4 + i] = h;
                    As[1][al_r][al_k + q * 4 + i] = l;
                }
            }
        }
        {
            const float* src = W + (size_t)(ck * 32 + wl_k) * FD + wl_n;
#pragma unroll
            for (int q = 0; q < 4; q++) {
                float4 v = *(const float4*)&src[q * 4];
                float f[4] = {v.x, v.y, v.z, v.w};
#pragma unroll
                for (int i = 0; i < 4; i++) {
                    __nv_bfloat16 h = __float2bfloat16(f[i]);
                    __nv_bfloat16 l = __float2bfloat16(f[i] - __bfloat162float(h));
                    Ws[0][wl_k][wl_n + q * 4 + i] = h;
                    Ws[1][wl_k][wl_n + q * 4 + i] = l;
                }
            }
        }
        __syncthreads();

#pragma unroll
        for (int ks = 0; ks < 32; ks += 16) {
            unsigned af[2][2][4];
#pragma unroll
            for (int v = 0; v < 2; v++)
#pragma unroll
                for (int mt = 0; mt < 2; mt++) {
                    int arow = m0 + mt * 16 + ((quad & 1) << 3) + r8;
                    int acol = ks + ((quad >> 1) << 3);
                    unsigned addr = (unsigned)__cvta_generic_to_shared(
                        &As[v][arow][acol]);
                    ldsm_x4(addr, af[v][mt][0], af[v][mt][1], af[v][mt][2], af[v][mt][3]);
                }
            unsigned bf[2][8][2];
#pragma unroll
            for (int v = 0; v < 2; v++)
#pragma unroll
                for (int nb = 0; nb < 4; nb++) {
                    int brow = ks + ((quad & 1) << 3) + r8;
                    int bcol = n0 + nb * 16 + ((quad >> 1) << 3);
                    unsigned addr = (unsigned)__cvta_generic_to_shared(
                        &Ws[v][brow][bcol]);
                    unsigned r0, r1, r2, r3;
                    ldsm_x4t(addr, r0, r1, r2, r3);
                    bf[v][nb * 2 + 0][0] = r0; bf[v][nb * 2 + 0][1] = r1;
                    bf[v][nb * 2 + 1][0] = r2; bf[v][nb * 2 + 1][1] = r3;
                }
#pragma unroll
            for (int mt = 0; mt < 2; mt++)
#pragma unroll
                for (int nt = 0; nt < 8; nt++) {
                    float* c = acc[mt][nt];
                    mma16816(c, af[0][mt][0], af[0][mt][1], af[0][mt][2], af[0][mt][3],
                             bf[0][nt][0], bf[0][nt][1]);
                    mma16816(c, af[0][mt][0], af[0][mt][1], af[0][mt][2], af[0][mt][3],
                             bf[1][nt][0], bf[1][nt][1]);
                    mma16816(c, af[1][mt][0], af[1][mt][1], af[1][mt][2], af[1][mt][3],
                             bf[0][nt][0], bf[0][nt][1]);
                }
        }
    }

#pragma unroll
    for (int mt = 0; mt < 2; mt++) {
        int lr = m0 + mt * 16 + (lane >> 2);
        int gr0 = USEIDX ? alive_s[lr] : (gbase + lr);
        int gr1 = USEIDX ? alive_s[lr + 8] : (gbase + lr + 8);
#pragma unroll
        for (int nt = 0; nt < 8; nt++) {
            int col = n0 + nt * 8 + ((lane & 3) << 1);
            float* c = acc[mt][nt];
            *(float2*)&d_H[(size_t)gr0 * FD + col] = make_float2(c[0], c[1]);
            *(float2*)&d_H[(size_t)gr1 * FD + col] = make_float2(c[2], c[3]);
        }
    }
}

// ---------------- GCN agg: padded CSR, u64 index batches, unroll 4 ----------
__global__ void __launch_bounds__(1024) k_agg(const float* __restrict__ bias,
                                              const float* __restrict__ p) {
    extern __shared__ float hs[];                    // [513][64]; row 512 = zeros
    __shared__ __align__(16) unsigned short csr_s[EPGP];
    __shared__ unsigned short off_s[NPG + 1];
    __shared__ float dinv_s[NPG], dinvm_s[NPG];

    int g = blockIdx.x, hf = blockIdx.y;
    int f0 = hf * 64;
    int tid = threadIdx.x;
    int gbase = g * NPG;

    if (tid < NPG) {
        dinv_s[tid] = d_dinv[gbase + tid];
        dinvm_s[tid] = d_dinvm[gbase + tid];
    }
    if (tid < NPG + 1) off_s[tid] = d_goff[g * (NPG + 1) + tid];
    {
        const uint4* gp = (const uint4*)(d_csr16 + g * EPGP);
        uint4* sp = (uint4*)csr_s;
        for (int j = tid; j < EPGP / 8; j += 1024) sp[j] = gp[j];
    }
    __syncthreads();

    for (int idx4 = tid; idx4 < 513 * 16; idx4 += 1024) {
        int row = idx4 >> 4, c4 = idx4 & 15;
        float m = (row < NPG) ? dinvm_s[row] : 0.f;
        float4 v = make_float4(0.f, 0.f, 0.f, 0.f);
        if (m != 0.f) {
            v = *(const float4*)&d_H[(size_t)(gbase + row) * FD + f0 + c4 * 4];
            v.x *= m; v.y *= m; v.z *= m; v.w *= m;
        }
        *(float4*)&hs[row * 64 + c4 * 4] = v;
    }
    __syncthreads();

    int w = tid >> 5, lane = tid & 31;
    float b0 = bias[f0 + 2 * lane], b1 = bias[f0 + 2 * lane + 1];
    float p0 = p[f0 + 2 * lane], p1 = p[f0 + 2 * lane + 1];
    const unsigned long long* cp64 = (const unsigned long long*)csr_s;

#pragma unroll 1
    for (int it = 0; it < 16; it++) {
        int d = (w << 4) + it;
        if (dinvm_s[d] == 0.f) continue;
        float dv = dinv_s[d];
        int q0 = off_s[d] >> 2, q1 = off_s[d + 1] >> 2;
        float acc0 = 0.f, acc1 = 0.f;
#pragma unroll 4
        for (int q = q0; q < q1; q++) {
            unsigned long long pk = cp64[q];
            int s0 = (int)(pk & 0xFFFFu);
            int s1 = (int)((pk >> 16) & 0xFFFFu);
            int s2 = (int)((pk >> 32) & 0xFFFFu);
            int s3 = (int)(pk >> 48);
            float2 h0 = *(const float2*)&hs[s0 * 64 + 2 * lane];
            float2 h1 = *(const float2*)&hs[s1 * 64 + 2 * lane];
            float2 h2 = *(const float2*)&hs[s2 * 64 + 2 * lane];
            float2 h3 = *(const float2*)&hs[s3 * 64 + 2 * lane];
            acc0 += h0.x + h1.x + h2.x + h3.x;
            acc1 += h0.y + h1.y + h2.y + h3.y;
        }
        float2 hd = *(const float2*)&hs[d * 64 + 2 * lane];
        float o0 = fmaxf(fmaf(dv, acc0 + hd.x, b0), 0.f);
        float o1 = fmaxf(fmaf(dv, acc1 + hd.y, b1), 0.f);
        *(float2*)&d_X[(size_t)(gbase + d) * FD + f0 + 2 * lane] = make_float2(o0, o1);
        float part = o0 * p0 + o1 * p1;
#pragma unroll
        for (int o = 16; o > 0; o >>= 1)
            part += __shfl_down_sync(0xffffffffu, part, o);
        if (lane == 0) atomicAdd(&d_sraw[gbase + d], part);
    }
}

// ---------------- top-k (1024 thr): register bitonic + gate + alive + dinv -----------
template <bool LAST>
__global__ void __launch_bounds__(1024) k_topk(int k, const float* __restrict__ p) {
    __shared__ unsigned long long keys[NPG];
    __shared__ float gate[NPG + 1];
    __shared__ float pp[128];
    __shared__ __align__(16) unsigned short csr_s[EPGP];
    __shared__ unsigned short off_s[NPG + 1];
    int g = blockIdx.x, tid = threadIdx.x;
    int gbase = g * NPG;

    if (!LAST) {
        const uint4* gp = (const uint4*)(d_csr16 + g * EPGP);
        uint4* sp = (uint4*)csr_s;
        for (int j = tid; j < EPGP / 8; j += 1024) sp[j] = gp[j];
        if (tid < NPG + 1) off_s[tid] = d_goff[g * (NPG + 1) + tid];
        if (tid == 0) gate[NPG] = 0.f;
    }

    if (tid < 128) { float v = p[tid]; pp[tid] = v * v; }
    __syncthreads();
    for (int o = 64; o > 0; o >>= 1) {
        if (tid < o && tid < 64) pp[tid] += pp[tid + o];
        __syncthreads();
    }
    float pinv = rsqrtf(pp[0]);

    unsigned long long mykey = 0;
    if (tid < NPG) {
        int i = tid;
        float m = d_dinvm[gbase + i];
        float raw = d_sraw[gbase + i];
        d_sraw[gbase + i] = 0.f;
        float sc = 1.f / (1.f + expf(-raw * pinv));
        d_score[gbase + i] = sc;
        unsigned int bs = __float_as_uint(sc);
        unsigned int u = (bs & 0x80000000u) ? ~bs : (bs | 0x80000000u);
        if (m == 0.f) u = 0u;
        mykey = ((unsigned long long)u << 32) | (unsigned int)(511 - i);
        gate[i] = 0.f;
    }

#pragma unroll
    for (int ksz = 2; ksz <= NPG; ksz <<= 1) {
        bool asc = (tid & ksz) != 0;
#pragma unroll
        for (int j = ksz >> 1; j > 0; j >>= 1) {
            unsigned long long partner;
            if (j >= 32) {
                __syncthreads();
                if (tid < NPG) keys[tid] = mykey;
                __syncthreads();
                partner = (tid < NPG) ? keys[tid ^ j] : 0ull;
            } else {
                partner = __shfl_xor_sync(0xffffffffu, mykey, j);
            }
            if (tid < NPG) {
                bool lower = (tid & j) == 0;
                unsigned long long a = lower ? mykey : partner;
                unsigned long long b = lower ? partner : mykey;
                bool swap = (a > b) == asc;
                mykey = lower ? (swap ? b : a) : (swap ? a : b);
            }
        }
    }

    if (tid < k) {
        int i = 511 - (int)(mykey & 0xFFFFFFFFull);
        gate[i] = 1.f;
        d_alive[g * k + tid] = gbase + i;
    }
    __syncthreads();

    if (!LAST) {
        if (tid < NPG) {
            int e0 = off_s[tid], e1 = off_s[tid + 1];
            float s = 0.f;
            for (int e = e0; e < e1; e++) s += gate[csr_s[e]];
            float m = gate[tid];
            float deg = m * (1.f + s);
            float dv = rsqrtf(fmaxf(deg, 1.f));
            d_dinv[gbase + tid] = dv;
            d_dinvm[gbase + tid] = m * dv;
        }
    }
}

// ---------------- readout: grid (NB,2) x 512 (16 warps), gather over alive ----------
__global__ void __launch_bounds__(512) k_read(int k) {
    __shared__ float smx[16][64], ssm[16][64];
    int g = blockIdx.x, hf = blockIdx.y;
    int f0 = hf * 64;
    int tid = threadIdx.x, w = tid >> 5, lane = tid & 31;   // 16 warps
    const int* alive = d_alive + g * k;
    float mx0 = -1e30f, mx1 = -1e30f, sm0 = 0.f, sm1 = 0.f;
#pragma unroll 4
    for (int j = w; j < k; j += 16) {
        int i = alive[j];
        float sc = d_score[i];
        float2 v = *(const float2*)&d_X[(size_t)i * FD + f0 + 2 * lane];
        float a = v.x * sc, b = v.y * sc;
        mx0 = fmaxf(mx0, a);
        mx1 = fmaxf(mx1, b);
        sm0 += a;
        sm1 += b;
    }
    smx[w][2 * lane] = mx0;
    smx[w][2 * lane + 1] = mx1;
    ssm[w][2 * lane] = sm0;
    ssm[w][2 * lane + 1] = sm1;
    __syncthreads();
    if (w == 0) {
#pragma unroll
        for (int s = 1; s < 16; s++) {
            mx0 = fmaxf(mx0, smx[s][2 * lane]);
            mx1 = fmaxf(mx1, smx[s][2 * lane + 1]);
            sm0 += ssm[s][2 * lane];
            sm1 += ssm[s][2 * lane + 1];
        }
        float ik = 1.f / (float)k;
        d_hg[g * 256 + f0 + 2 * lane]           += fmaxf(mx0, 0.f);
        d_hg[g * 256 + f0 + 2 * lane + 1]       += fmaxf(mx1, 0.f);
        d_hg[g * 256 + 128 + f0 + 2 * lane]     += fmaxf(sm0 * ik, 0.f);
        d_hg[g * 256 + 128 + f0 + 2 * lane + 1] += fmaxf(sm1 * ik, 0.f);
    }
}

// ---------------- fused MLP head ----------------
__global__ void __launch_bounds__(256) k_head(const float* __restrict__ inp_c,
                                              const float* __restrict__ We,
                                              const float* __restrict__ Wa,
                                              const float* __restrict__ ba,
                                              const float* __restrict__ Wb,
                                              const float* __restrict__ bb,
                                              const float* __restrict__ Wc,
                                              float* __restrict__ out) {
    __shared__ float fu[320];
    __shared__ float h1[256];
    __shared__ float h2[128];
    __shared__ float red[128];
    int g = blockIdx.x, tid = threadIdx.x;

    if (tid < 64) {
        float a = 0.f;
        for (int i = 0; i < 64; i++) a += inp_c[g * 64 + i] * We[i * 64 + tid];
        fu[tid] = fmaxf(a, 0.f);
    }
    fu[64 + tid] = d_hg[g * 256 + tid];
    __syncthreads();

    float a = ba[tid];
    for (int i = 0; i < 320; i++) a += fu[i] * Wa[i * 256 + tid];
    h1[tid] = fmaxf(a, 0.f);
    __syncthreads();

    if (tid < 128) {
        float c = bb[tid];
        for (int i = 0; i < 256; i++) c += h1[i] * Wb[i * 128 + tid];
        h2[tid] = fmaxf(c, 0.f);
    }
    __syncthreads();

    if (tid < 128) red[tid] = h2[tid] * Wc[tid];
    __syncthreads();
    for (int o = 64; o > 0; o >>= 1) {
        if (tid < o) red[tid] += red[tid + o];
        __syncthreads();
    }
    if (tid == 0) out[g] = red[0];
}

// ---------------- launch ----------------
extern "C" void kernel_launch(void* const* d_in, const int* in_sizes, int n_in,
                              void* d_out, int out_size) {
    const float* x     = (const float*)d_in[0];
    const float* inp_c = (const float*)d_in[1];
    const int*   ei    = (const int*)d_in[2];
    const int*   src   = ei;
    const int*   dst   = ei + EE;
    const float* W1 = (const float*)d_in[4];
    const float* b1 = (const float*)d_in[5];
    const float* W2 = (const float*)d_in[6];
    const float* b2 = (const float*)d_in[7];
    const float* W3 = (const float*)d_in[8];
    const float* b3 = (const float*)d_in[9];
    const float* p1 = (const float*)d_in[10];
    const float* p2 = (const float*)d_in[11];
    const float* p3 = (const float*)d_in[12];
    const float* We = (const float*)d_in[13];
    const float* Wa = (const float*)d_in[14];
    const float* ba = (const float*)d_in[15];
    const float* Wb = (const float*)d_in[16];
    const float* bb = (const float*)d_in[17];
    const float* Wc = (const float*)d_in[18];
    float* out = (float*)d_out;

    cudaFuncSetAttribute((const void*)k_agg,
                         cudaFuncAttributeMaxDynamicSharedMemorySize, 140000);
    size_t aggsm = 513 * 64 * sizeof(float);

    k_csr<<<NB, 512>>>(src, dst);

    // ---- layer 1 ----
    k_gemm<false, false><<<NN / 128, 256>>>(x, W1);
    k_agg<<<dim3(NB, 2), 1024, aggsm>>>(b1, p1);
    k_topk<false><<<NB, 1024>>>(256, p1);
    k_read<<<dim3(NB, 2), 512>>>(256);

    // ---- layer 2 (32768 alive rows, gated A) ----
    k_gemm<true, true><<<(NB * 256) / 128, 256>>>(nullptr, W2);
    k_agg<<<dim3(NB, 2), 1024, aggsm>>>(b2, p2);
    k_topk<false><<<NB, 1024>>>(128, p2);
    k_read<<<dim3(NB, 2), 512>>>(128);

    // ---- layer 3 (16384 alive rows, gated A) ----
    k_gemm<true, true><<<(NB * 128) / 128, 256>>>(nullptr, W3);
    k_agg<<<dim3(NB, 2), 1024, aggsm>>>(b3, p3);
    k_topk<true><<<NB, 1024>>>(64, p3);
    k_read<<<dim3(NB, 2), 512>>>(64);

    // ---- head ----
    k_head<<<NB, 256>>>(inp_c, We, Wa, ba, Wb, bb, Wc, out);
}

// round 17
// speedup vs baseline: 1.0254x; 1.0254x over previous
#include <cuda_runtime.h>
#include <cuda_bf16.h>

#define NN 65536      // total nodes
#define EE 1048576    // total edges
#define NB 128        // graphs
#define NPG 512       // nodes per graph
#define EPG 8192      // edges per graph (N*DEG)
#define EPGP 10240    // padded edges per graph (rows padded to x4)
#define FD 128        // feature dim

// ---------------- device scratch ----------------
__device__ __align__(256) float d_X[NN * FD];
__device__ __align__(256) float d_H[NN * FD];
__device__ __align__(256) float d_score[NN];
__device__ __align__(256) float d_sraw[NN];
__device__ __align__(256) float d_dinv[NN];
__device__ __align__(256) float d_dinvm[NN];
__device__ __align__(256) unsigned short d_csrA[NB * EPGP];
__device__ __align__(256) unsigned short d_csrB[NB * EPGP];
__device__ __align__(256) unsigned short d_goffA[NB * (NPG + 1)];
__device__ __align__(256) unsigned short d_goffB[NB * (NPG + 1)];
__device__ __align__(256) int   d_alive[NB * 256];
__device__ __align__(256) float d_hg[NB * 256];

// ---------------- per-graph CSR build (rows padded to x4) + layer-1 dinv + init ------
__global__ void __launch_bounds__(512) k_csr(const int* __restrict__ src,
                                             const int* __restrict__ dst) {
    __shared__ unsigned short s_src[EPG];
    __shared__ unsigned short s_dst[EPG];
    __shared__ int cnt[NPG];
    __shared__ int scn[NPG];
    __shared__ int cur[NPG];
    int g = blockIdx.x, tid = threadIdx.x;
    int gb = g * NPG, eb = g * EPG, ebp = g * EPGP;

    cnt[tid] = 0;
    for (int e = tid; e < EPG; e += 512) {
        s_src[e] = (unsigned short)(src[eb + e] - gb);
        s_dst[e] = (unsigned short)(dst[eb + e] - gb);
    }
    __syncthreads();
    for (int e = tid; e < EPG; e += 512) atomicAdd(&cnt[s_dst[e]], 1);
    __syncthreads();
    int c = cnt[tid];
    int cp = (c + 3) & ~3;
    scn[tid] = cp;
    __syncthreads();
    for (int o = 1; o < 512; o <<= 1) {
        int a = scn[tid];
        int b = (tid >= o) ? scn[tid - o] : 0;
        __syncthreads();
        scn[tid] = a + b;
        __syncthreads();
    }
    int excl = scn[tid] - cp;
    cur[tid] = excl;
    d_goffA[g * (NPG + 1) + tid] = (unsigned short)excl;
    if (tid == 511) d_goffA[g * (NPG + 1) + NPG] = (unsigned short)scn[511];

    for (int j = excl + c; j < excl + cp; j++) d_csrA[ebp + j] = (unsigned short)NPG;

    float dv = rsqrtf((float)(1 + c));
    d_dinv[gb + tid] = dv;
    d_dinvm[gb + tid] = dv;

    d_sraw[gb + tid] = 0.f;
    if (tid < 256) d_hg[g * 256 + tid] = 0.f;
    __syncthreads();
    for (int e = tid; e < EPG; e += 512) {
        int d = s_dst[e];
        int pos = atomicAdd(&cur[d], 1);
        d_csrA[ebp + pos] = s_src[e];
    }
}

// ---------------- tensor-core GEMM: H[rows] = gate*A[rows] @ W -------------------
__device__ __forceinline__ void ldsm_x4(unsigned addr, unsigned& r0, unsigned& r1,
                                        unsigned& r2, unsigned& r3) {
    asm volatile("ldmatrix.sync.aligned.m8n8.x4.shared.b16 {%0,%1,%2,%3}, [%4];"
                 : "=r"(r0), "=r"(r1), "=r"(r2), "=r"(r3) : "r"(addr));
}
__device__ __forceinline__ void ldsm_x4t(unsigned addr, unsigned& r0, unsigned& r1,
                                         unsigned& r2, unsigned& r3) {
    asm volatile("ldmatrix.sync.aligned.m8n8.x4.trans.shared.b16 {%0,%1,%2,%3}, [%4];"
                 : "=r"(r0), "=r"(r1), "=r"(r2), "=r"(r3) : "r"(addr));
}
__device__ __forceinline__ void mma16816(float* c, unsigned a0, unsigned a1,
                                         unsigned a2, unsigned a3,
                                         unsigned b0, unsigned b1) {
    asm volatile(
        "mma.sync.aligned.m16n8k16.row.col.f32.bf16.bf16.f32 "
        "{%0,%1,%2,%3},{%4,%5,%6,%7},{%8,%9},{%0,%1,%2,%3};"
        : "+f"(c[0]), "+f"(c[1]), "+f"(c[2]), "+f"(c[3])
        : "r"(a0), "r"(a1), "r"(a2), "r"(a3), "r"(b0), "r"(b1));
}

#define APAD 40
#define WPAD 136

template <bool USEIDX, bool GATE>
__global__ void __launch_bounds__(256) k_gemm(const float* __restrict__ Ain,
                                              const float* __restrict__ W) {
    __shared__ __align__(16) __nv_bfloat16 As[2][128][APAD];
    __shared__ __align__(16) __nv_bfloat16 Ws[2][32][WPAD];
    __shared__ int alive_s[128];

    const int tid = threadIdx.x;
    const int gbase = blockIdx.x * 128;

    if (USEIDX && tid < 128) alive_s[tid] = d_alive[gbase + tid];

    const int al_r = tid >> 1, al_k = (tid & 1) * 16;
    const int wl_k = tid >> 3, wl_n = (tid & 7) * 16;
    int garow = USEIDX ? d_alive[gbase + al_r] : (gbase + al_r);
    float gate = GATE ? d_score[garow] : 1.f;
    const float* Arow = (USEIDX ? (const float*)d_X : Ain) + (size_t)garow * FD;

    const int lane = tid & 31, wid = tid >> 5;
    const int m0 = (wid >> 1) * 32;
    const int n0 = (wid & 1) * 64;
    const int quad = lane >> 3, r8 = lane & 7;

    float acc[2][8][4] = {};

#pragma unroll 1
    for (int ck = 0; ck < 4; ck++) {
        if (ck) __syncthreads();
        {
            const float* src = Arow + ck * 32 + al_k;
#pragma unroll
            for (int q = 0; q < 4; q++) {
                float4 v = *(const float4*)&src[q * 4];
                if (GATE) { v.x *= gate; v.y *= gate; v.z *= gate; v.w *= gate; }
                float f[4] = {v.x, v.y, v.z, v.w};
#pragma unroll
                for (int i = 0; i < 4; i++) {
                    __nv_bfloat16 h = __float2bfloat16(f[i]);
                    __nv_bfloat16 l = __float2bfloat16(f[i] - __bfloat162float(h));
                    As[0][al_r][al_k + q * 4 + i] = h;
                    As[1][al_r][al_k + q * 4 + i] = l;
                }
            }
        }
        {
            const float* src = W + (size_t)(ck * 32 + wl_k) * FD + wl_n;
#pragma unroll
            for (int q = 0; q < 4; q++) {
                float4 v = *(const float4*)&src[q * 4];
                float f[4] = {v.x, v.y, v.z, v.w};
#pragma unroll
                for (int i = 0; i < 4; i++) {
                    __nv_bfloat16 h = __float2bfloat16(f[i]);
                    __nv_bfloat16 l = __float2bfloat16(f[i] - __bfloat162float(h));
                    Ws[0][wl_k][wl_n + q * 4 + i] = h;
                    Ws[1][wl_k][wl_n + q * 4 + i] = l;
                }
            }
        }
        __syncthreads();

#pragma unroll
        for (int ks = 0; ks < 32; ks += 16) {
            unsigned af[2][2][4];
#pragma unroll
            for (int v = 0; v < 2; v++)
#pragma unroll
                for (int mt = 0; mt < 2; mt++) {
                    int arow = m0 + mt * 16 + ((quad & 1) << 3) + r8;
                    int acol = ks + ((quad >> 1) << 3);
                    unsigned addr = (unsigned)__cvta_generic_to_shared(
                        &As[v][arow][acol]);
                    ldsm_x4(addr, af[v][mt][0], af[v][mt][1], af[v][mt][2], af[v][mt][3]);
                }
            unsigned bf[2][8][2];
#pragma unroll
            for (int v = 0; v < 2; v++)
#pragma unroll
                for (int nb = 0; nb < 4; nb++) {
                    int brow = ks + ((quad & 1) << 3) + r8;
                    int bcol = n0 + nb * 16 + ((quad >> 1) << 3);
                    unsigned addr = (unsigned)__cvta_generic_to_shared(
                        &Ws[v][brow][bcol]);
                    unsigned r0, r1, r2, r3;
                    ldsm_x4t(addr, r0, r1, r2, r3);
                    bf[v][nb * 2 + 0][0] = r0; bf[v][nb * 2 + 0][1] = r1;
                    bf[v][nb * 2 + 1][0] = r2; bf[v][nb * 2 + 1][1] = r3;
                }
#pragma unroll
            for (int mt = 0; mt < 2; mt++)
#pragma unroll
                for (int nt = 0; nt < 8; nt++) {
                    float* c = acc[mt][nt];
                    mma16816(c, af[0][mt][0], af[0][mt][1], af[0][mt][2], af[0][mt][3],
                             bf[0][nt][0], bf[0][nt][1]);
                    mma16816(c, af[0][mt][0], af[0][mt][1], af[0][mt][2], af[0][mt][3],
                             bf[1][nt][0], bf[1][nt][1]);
                    mma16816(c, af[1][mt][0], af[1][mt][1], af[1][mt][2], af[1][mt][3],
                             bf[0][nt][0], bf[0][nt][1]);
                }
        }
    }

#pragma unroll
    for (int mt = 0; mt < 2; mt++) {
        int lr = m0 + mt * 16 + (lane >> 2);
        int gr0 = USEIDX ? alive_s[lr] : (gbase + lr);
        int gr1 = USEIDX ? alive_s[lr + 8] : (gbase + lr + 8);
#pragma unroll
        for (int nt = 0; nt < 8; nt++) {
            int col = n0 + nt * 8 + ((lane & 3) << 1);
            float* c = acc[mt][nt];
            *(float2*)&d_H[(size_t)gr0 * FD + col] = make_float2(c[0], c[1]);
            *(float2*)&d_H[(size_t)gr1 * FD + col] = make_float2(c[2], c[3]);
        }
    }
}

// ---------------- GCN agg: padded CSR (buffer SRC), u64 index batches ----------
template <int SRC>
__global__ void __launch_bounds__(1024) k_agg(const float* __restrict__ bias,
                                              const float* __restrict__ p) {
    extern __shared__ float hs[];                    // [513][64]; row 512 = zeros
    __shared__ __align__(16) unsigned short csr_s[EPGP];
    __shared__ unsigned short off_s[NPG + 1];
    __shared__ float dinv_s[NPG], dinvm_s[NPG];

    const unsigned short* csrg = SRC ? d_csrB : d_csrA;
    const unsigned short* goff = SRC ? d_goffB : d_goffA;

    int g = blockIdx.x, hf = blockIdx.y;
    int f0 = hf * 64;
    int tid = threadIdx.x;
    int gbase = g * NPG;

    if (tid < NPG) {
        dinv_s[tid] = d_dinv[gbase + tid];
        dinvm_s[tid] = d_dinvm[gbase + tid];
    }
    if (tid < NPG + 1) off_s[tid] = goff[g * (NPG + 1) + tid];
    __syncthreads();
    {
        int tot8 = ((int)off_s[NPG] + 7) >> 3;       // only copy used entries
        const uint4* gp = (const uint4*)(csrg + g * EPGP);
        uint4* sp = (uint4*)csr_s;
        for (int j = tid; j < tot8; j += 1024) sp[j] = gp[j];
    }

    for (int idx4 = tid; idx4 < 513 * 16; idx4 += 1024) {
        int row = idx4 >> 4, c4 = idx4 & 15;
        float m = (row < NPG) ? dinvm_s[row] : 0.f;
        float4 v = make_float4(0.f, 0.f, 0.f, 0.f);
        if (m != 0.f) {
            v = *(const float4*)&d_H[(size_t)(gbase + row) * FD + f0 + c4 * 4];
            v.x *= m; v.y *= m; v.z *= m; v.w *= m;
        }
        *(float4*)&hs[row * 64 + c4 * 4] = v;
    }
    __syncthreads();

    int w = tid >> 5, lane = tid & 31;
    float b0 = bias[f0 + 2 * lane], b1 = bias[f0 + 2 * lane + 1];
    float p0 = p[f0 + 2 * lane], p1 = p[f0 + 2 * lane + 1];
    const unsigned long long* cp64 = (const unsigned long long*)csr_s;

#pragma unroll 1
    for (int it = 0; it < 16; it++) {
        int d = (w << 4) + it;
        if (dinvm_s[d] == 0.f) continue;
        float dv = dinv_s[d];
        int q0 = off_s[d] >> 2, q1 = off_s[d + 1] >> 2;
        float acc0 = 0.f, acc1 = 0.f;
#pragma unroll 2
        for (int q = q0; q < q1; q++) {
            unsigned long long pk = cp64[q];
            int s0 = (int)(pk & 0xFFFFu);
            int s1 = (int)((pk >> 16) & 0xFFFFu);
            int s2 = (int)((pk >> 32) & 0xFFFFu);
            int s3 = (int)(pk >> 48);
            float2 h0 = *(const float2*)&hs[s0 * 64 + 2 * lane];
            float2 h1 = *(const float2*)&hs[s1 * 64 + 2 * lane];
            float2 h2 = *(const float2*)&hs[s2 * 64 + 2 * lane];
            float2 h3 = *(const float2*)&hs[s3 * 64 + 2 * lane];
            acc0 += h0.x + h1.x + h2.x + h3.x;
            acc1 += h0.y + h1.y + h2.y + h3.y;
        }
        float2 hd = *(const float2*)&hs[d * 64 + 2 * lane];
        float o0 = fmaxf(fmaf(dv, acc0 + hd.x, b0), 0.f);
        float o1 = fmaxf(fmaf(dv, acc1 + hd.y, b1), 0.f);
        *(float2*)&d_X[(size_t)(gbase + d) * FD + f0 + 2 * lane] = make_float2(o0, o1);
        float part = o0 * p0 + o1 * p1;
#pragma unroll
        for (int o = 16; o > 0; o >>= 1)
            part += __shfl_down_sync(0xffffffffu, part, o);
        if (lane == 0) atomicAdd(&d_sraw[gbase + d], part);
    }
}

// ------- top-k (1024 thr): bitonic + gate + alive + dinv + CSR COMPACTION ---------
// Reads CSR buffer SRC, writes compacted alive-alive CSR to the other buffer.
template <bool LAST, int SRC>
__global__ void __launch_bounds__(1024) k_topk(int k, const float* __restrict__ p) {
    __shared__ unsigned long long keys[NPG];
    __shared__ float gate[NPG + 1];
    __shared__ float pp[128];
    __shared__ __align__(16) unsigned short csr_s[EPGP];
    __shared__ unsigned short off_s[NPG + 1];
    __shared__ int scn[NPG];
    int g = blockIdx.x, tid = threadIdx.x;
    int gbase = g * NPG;
    int ebp = g * EPGP;

    const unsigned short* csrg = SRC ? d_csrB : d_csrA;
    const unsigned short* goff = SRC ? d_goffB : d_goffA;
    unsigned short* csro = SRC ? d_csrA : d_csrB;
    unsigned short* goffo = SRC ? d_goffA : d_goffB;

    if (!LAST) {
        if (tid < NPG + 1) off_s[tid] = goff[g * (NPG + 1) + tid];
    }
    if (tid < 128) { float v = p[tid]; pp[tid] = v * v; }
    __syncthreads();
    if (!LAST) {
        int tot8 = ((int)off_s[NPG] + 7) >> 3;
        const uint4* gp = (const uint4*)(csrg + g * EPGP);
        uint4* sp = (uint4*)csr_s;
        for (int j = tid; j < tot8; j += 1024) sp[j] = gp[j];
        if (tid == 0) gate[NPG] = 0.f;
    }
    for (int o = 64; o > 0; o >>= 1) {
        if (tid < o && tid < 64) pp[tid] += pp[tid + o];
        __syncthreads();
    }
    float pinv = rsqrtf(pp[0]);

    unsigned long long mykey = 0;
    if (tid < NPG) {
        int i = tid;
        float m = d_dinvm[gbase + i];
        float raw = d_sraw[gbase + i];
        d_sraw[gbase + i] = 0.f;
        float sc = 1.f / (1.f + expf(-raw * pinv));
        d_score[gbase + i] = sc;
        unsigned int bs = __float_as_uint(sc);
        unsigned int u = (bs & 0x80000000u) ? ~bs : (bs | 0x80000000u);
        if (m == 0.f) u = 0u;
        mykey = ((unsigned long long)u << 32) | (unsigned int)(511 - i);
        gate[i] = 0.f;
    }

#pragma unroll
    for (int ksz = 2; ksz <= NPG; ksz <<= 1) {
        bool asc = (tid & ksz) != 0;
#pragma unroll
        for (int j = ksz >> 1; j > 0; j >>= 1) {
            unsigned long long partner;
            if (j >= 32) {
                __syncthreads();
                if (tid < NPG) keys[tid] = mykey;
                __syncthreads();
                partner = (tid < NPG) ? keys[tid ^ j] : 0ull;
            } else {
                partner = __shfl_xor_sync(0xffffffffu, mykey, j);
            }
            if (tid < NPG) {
                bool lower = (tid & j) == 0;
                unsigned long long a = lower ? mykey : partner;
                unsigned long long b = lower ? partner : mykey;
                bool swap = (a > b) == asc;
                mykey = lower ? (swap ? b : a) : (swap ? a : b);
            }
        }
    }

    if (tid < k) {
        int i = 511 - (int)(mykey & 0xFFFFFFFFull);
        gate[i] = 1.f;
        d_alive[g * k + tid] = gbase + i;
    }
    __syncthreads();

    if (!LAST) {
        // degrees + alive-edge counts from the new gate
        int e0 = 0, e1 = 0, cnt = 0;
        float m = 0.f;
        if (tid < NPG) {
            e0 = off_s[tid];
            e1 = off_s[tid + 1];
            m = gate[tid];
            float s = 0.f;
            if (m != 0.f) {
                for (int e = e0; e < e1; e++) {
                    float gv = gate[csr_s[e]];
                    s += gv;
                    cnt += (gv != 0.f);
                }
            }
            float deg = m * (1.f + s);
            float dv = rsqrtf(fmaxf(deg, 1.f));
            d_dinv[gbase + tid] = dv;
            d_dinvm[gbase + tid] = m * dv;
        }
        // block scan of padded counts (512 rows)
        int cp = (cnt + 3) & ~3;
        if (tid < NPG) scn[tid] = cp;
        __syncthreads();
        for (int o = 1; o < 512; o <<= 1) {
            int a = 0;
            if (tid < NPG) {
                a = scn[tid];
                if (tid >= o) a += scn[tid - o];
            }
            __syncthreads();
            if (tid < NPG) scn[tid] = a;
            __syncthreads();
        }
        if (tid < NPG) {
            int excl = scn[tid] - cp;
            goffo[g * (NPG + 1) + tid] = (unsigned short)excl;
            if (tid == NPG - 1) goffo[g * (NPG + 1) + NPG] = (unsigned short)scn[NPG - 1];
            // scatter surviving edges + pad
            int pos = excl;
            if (m != 0.f) {
                for (int e = e0; e < e1; e++) {
                    int sl = csr_s[e];
                    if (gate[sl] != 0.f) csro[ebp + pos++] = (unsigned short)sl;
                }
            }
            int end = excl + cp;
            for (; pos < end; pos++) csro[ebp + pos] = (unsigned short)NPG;
        }
    }
}

// ---------------- readout: grid (NB,2) x 512 (16 warps), gather over alive ----------
__global__ void __launch_bounds__(512) k_read(int k) {
    __shared__ float smx[16][64], ssm[16][64];
    int g = blockIdx.x, hf = blockIdx.y;
    int f0 = hf * 64;
    int tid = threadIdx.x, w = tid >> 5, lane = tid & 31;
    const int* alive = d_alive + g * k;
    float mx0 = -1e30f, mx1 = -1e30f, sm0 = 0.f, sm1 = 0.f;
#pragma unroll 4
    for (int j = w; j < k; j += 16) {
        int i = alive[j];
        float sc = d_score[i];
        float2 v = *(const float2*)&d_X[(size_t)i * FD + f0 + 2 * lane];
        float a = v.x * sc, b = v.y * sc;
        mx0 = fmaxf(mx0, a);
        mx1 = fmaxf(mx1, b);
        sm0 += a;
        sm1 += b;
    }
    smx[w][2 * lane] = mx0;
    smx[w][2 * lane + 1] = mx1;
    ssm[w][2 * lane] = sm0;
    ssm[w][2 * lane + 1] = sm1;
    __syncthreads();
    if (w == 0) {
#pragma unroll
        for (int s = 1; s < 16; s++) {
            mx0 = fmaxf(mx0, smx[s][2 * lane]);
            mx1 = fmaxf(mx1, smx[s][2 * lane + 1]);
            sm0 += ssm[s][2 * lane];
            sm1 += ssm[s][2 * lane + 1];
        }
        float ik = 1.f / (float)k;
        d_hg[g * 256 + f0 + 2 * lane]           += fmaxf(mx0, 0.f);
        d_hg[g * 256 + f0 + 2 * lane + 1]       += fmaxf(mx1, 0.f);
        d_hg[g * 256 + 128 + f0 + 2 * lane]     += fmaxf(sm0 * ik, 0.f);
        d_hg[g * 256 + 128 + f0 + 2 * lane + 1] += fmaxf(sm1 * ik, 0.f);
    }
}

// ---------------- fused MLP head ----------------
__global__ void __launch_bounds__(256) k_head(const float* __restrict__ inp_c,
                                              const float* __restrict__ We,
                                              const float* __restrict__ Wa,
                                              const float* __restrict__ ba,
                                              const float* __restrict__ Wb,
                                              const float* __restrict__ bb,
                                              const float* __restrict__ Wc,
                                              float* __restrict__ out) {
    __shared__ float fu[320];
    __shared__ float h1[256];
    __shared__ float h2[128];
    __shared__ float red[128];
    int g = blockIdx.x, tid = threadIdx.x;

    if (tid < 64) {
        float a = 0.f;
        for (int i = 0; i < 64; i++) a += inp_c[g * 64 + i] * We[i * 64 + tid];
        fu[tid] = fmaxf(a, 0.f);
    }
    fu[64 + tid] = d_hg[g * 256 + tid];
    __syncthreads();

    float a = ba[tid];
    for (int i = 0; i < 320; i++) a += fu[i] * Wa[i * 256 + tid];
    h1[tid] = fmaxf(a, 0.f);
    __syncthreads();

    if (tid < 128) {
        float c = bb[tid];
        for (int i = 0; i < 256; i++) c += h1[i] * Wb[i * 128 + tid];
        h2[tid] = fmaxf(c, 0.f);
    }
    __syncthreads();

    if (tid < 128) red[tid] = h2[tid] * Wc[tid];
    __syncthreads();
    for (int o = 64; o > 0; o >>= 1) {
        if (tid < o) red[tid] += red[tid + o];
        __syncthreads();
    }
    if (tid == 0) out[g] = red[0];
}

// ---------------- launch ----------------
extern "C" void kernel_launch(void* const* d_in, const int* in_sizes, int n_in,
                              void* d_out, int out_size) {
    const float* x     = (const float*)d_in[0];
    const float* inp_c = (const float*)d_in[1];
    const int*   ei    = (const int*)d_in[2];
    const int*   src   = ei;
    const int*   dst   = ei + EE;
    const float* W1 = (const float*)d_in[4];
    const float* b1 = (const float*)d_in[5];
    const float* W2 = (const float*)d_in[6];
    const float* b2 = (const float*)d_in[7];
    const float* W3 = (const float*)d_in[8];
    const float* b3 = (const float*)d_in[9];
    const float* p1 = (const float*)d_in[10];
    const float* p2 = (const float*)d_in[11];
    const float* p3 = (const float*)d_in[12];
    const float* We = (const float*)d_in[13];
    const float* Wa = (const float*)d_in[14];
    const float* ba = (const float*)d_in[15];
    const float* Wb = (const float*)d_in[16];
    const float* bb = (const float*)d_in[17];
    const float* Wc = (const float*)d_in[18];
    float* out = (float*)d_out;

    cudaFuncSetAttribute((const void*)k_agg<0>,
                         cudaFuncAttributeMaxDynamicSharedMemorySize, 140000);
    cudaFuncSetAttribute((const void*)k_agg<1>,
                         cudaFuncAttributeMaxDynamicSharedMemorySize, 140000);
    size_t aggsm = 513 * 64 * sizeof(float);

    k_csr<<<NB, 512>>>(src, dst);

    // ---- layer 1 (CSR buffer A) ----
    k_gemm<false, false><<<NN / 128, 256>>>(x, W1);
    k_agg<0><<<dim3(NB, 2), 1024, aggsm>>>(b1, p1);
    k_topk<false, 0><<<NB, 1024>>>(256, p1);        // compacts A -> B
    k_read<<<dim3(NB, 2), 512>>>(256);

    // ---- layer 2 (CSR buffer B, ~2K alive edges/graph) ----
    k_gemm<true, true><<<(NB * 256) / 128, 256>>>(nullptr, W2);
    k_agg<1><<<dim3(NB, 2), 1024, aggsm>>>(b2, p2);
    k_topk<false, 1><<<NB, 1024>>>(128, p2);        // compacts B -> A
    k_read<<<dim3(NB, 2), 512>>>(128);

    // ---- layer 3 (CSR buffer A, ~600 alive edges/graph) ----
    k_gemm<true, true><<<(NB * 128) / 128, 256>>>(nullptr, W3);
    k_agg<0><<<dim3(NB, 2), 1024, aggsm>>>(b3, p3);
    k_topk<true, 0><<<NB, 1024>>>(64, p3);
    k_read<<<dim3(NB, 2), 512>>>(64);

    // ---- head ----
    k_head<<<NB, 256>>>(inp_c, We, Wa, ba, Wb, bb, Wc, out);
}